// round 10
// baseline (speedup 1.0000x reference)
#include <cuda_runtime.h>
#include <cstdint>
#include <cfloat>

#define B_   16
#define N_   4096
#define M_   1024
#define KNN_ 32
#define P_   (B_*M_*KNN_)   // 524288

typedef unsigned long long ull;

// ---------------- device scratch (no allocation allowed) ----------------
__device__ float g_featT[B_*N_*64];      // [b][n][c]
__device__ int   g_idx[P_];
__device__ float g_y1[P_*64];
__device__ float g_y2[P_*64];
__device__ float g_mx[B_*M_*128];        // per (b,m,o) max over k
__device__ float g_mn[B_*M_*128];        // per (b,m,o) min over k
__device__ float g_p1s[64*4096], g_p1q[64*4096];   // [ch][blk] transposed
__device__ float g_p2s[64*4096], g_p2q[64*4096];
__device__ float g_p3s[128*8192], g_p3q[128*8192];
__device__ float g_bn1[128];   // [0:64) scale, [64:128) shift
__device__ float g_bn2[128];
__device__ float g_bn3[256];

// ---------------- f32x2 helpers ----------------
__device__ __forceinline__ ull pk(float a, float b) {
    ull r; asm("mov.b64 %0, {%1, %2};" : "=l"(r) : "f"(a), "f"(b)); return r;
}
__device__ __forceinline__ void fma2(ull& d, ull a, ull b) {
    asm("fma.rn.f32x2 %0, %1, %2, %0;" : "+l"(d) : "l"(a), "l"(b));
}
__device__ __forceinline__ float2 unpk(ull v) {
    float2 f; asm("mov.b64 {%0, %1}, %2;" : "=f"(f.x), "=f"(f.y) : "l"(v)); return f;
}

// ---------------- fused pre-pass: transpose (blocks 0..4095) + KNN ----------------
__device__ __forceinline__ unsigned fkey(float f) {
    unsigned u = __float_as_uint(f);
    return (u & 0x80000000u) ? ~u : (u | 0x80000000u);
}

__global__ void k_pre(const float* __restrict__ f, const float* __restrict__ loc,
                      const float* __restrict__ nl) {
    __shared__ unsigned keys[N_];
    __shared__ unsigned hist[256];
    __shared__ unsigned sh_pfx;
    __shared__ int sh_r, sh_no, sh_ne;
    __shared__ int outb[32];
    __shared__ int eqb[128];
    int bi = blockIdx.x, tid = threadIdx.x;

    if (bi < 4096) {   // transpose features [b][c][n] -> [b][n][c]
        float (*tsh)[33] = (float(*)[33])keys;    // 32x33 fits in keys
        int n0 = (bi & 127) * 32, c0 = ((bi >> 7) & 1) * 32, b = bi >> 8;
        int tx = tid & 31, ty = tid >> 5;
#pragma unroll
        for (int i = 0; i < 8; i++)
            tsh[ty + i*4][tx] = f[((size_t)b*64 + c0 + ty + i*4) * N_ + n0 + tx];
        __syncthreads();
#pragma unroll
        for (int i = 0; i < 8; i++)
            g_featT[((size_t)b*N_ + n0 + ty + i*4) * 64 + c0 + tx] = tsh[tx][ty + i*4];
        return;
    }

    int qb = bi - 4096;
    int m = qb & (M_-1), b = qb >> 10;

    float qx = nl[(b*M_+m)*3+0], qy = nl[(b*M_+m)*3+1], qz = nl[(b*M_+m)*3+2];
    float q2 = qx*qx + qy*qy + qz*qz;
    for (int i = tid; i < N_; i += 128) {
        float lx = loc[(b*N_+i)*3+0], ly = loc[(b*N_+i)*3+1], lz = loc[(b*N_+i)*3+2];
        float x2 = lx*lx + ly*ly + lz*lz;
        float dot = qx*lx + qy*ly + qz*lz;
        keys[i] = fkey(q2 + x2 - 2.0f*dot);
    }
    if (tid == 0) { sh_pfx = 0u; sh_r = 31; sh_no = 0; sh_ne = 0; }
    __syncthreads();

    for (int sh = 24; sh >= 0; sh -= 8) {
        for (int i = tid; i < 256; i += 128) hist[i] = 0u;
        __syncthreads();
        unsigned pfx = sh_pfx;
        unsigned hm = (sh == 24) ? 0u : (0xFFFFFFFFu << (sh + 8));
        for (int i = tid; i < N_; i += 128) {
            unsigned k = keys[i];
            if ((k & hm) == pfx) atomicAdd(&hist[(k >> sh) & 255], 1u);
        }
        __syncthreads();
        if (tid == 0) {
            int r = sh_r; unsigned c = 0;
            for (int d = 0; d < 256; d++) {
                unsigned h = hist[d];
                if (c + h > (unsigned)r) { sh_pfx = pfx | ((unsigned)d << sh); sh_r = r - (int)c; break; }
                c += h;
            }
        }
        __syncthreads();
    }
    unsigned T = sh_pfx;
    for (int i = tid; i < N_; i += 128) {
        unsigned k = keys[i];
        if (k < T) { int p = atomicAdd(&sh_no, 1); outb[p] = i; }
        else if (k == T) { int p = atomicAdd(&sh_ne, 1); if (p < 128) eqb[p] = i; }
    }
    __syncthreads();
    if (tid == 0) {
        int need = 32 - sh_no, ne = sh_ne < 128 ? sh_ne : 128;
        for (int t = 0; t < need; t++) {
            int best = 0x7fffffff, bj = 0;
            for (int j = 0; j < ne; j++) if (eqb[j] < best) { best = eqb[j]; bj = j; }
            outb[sh_no + t] = best; eqb[bj] = 0x7fffffff;
        }
    }
    __syncthreads();
    if (tid < 32) {   // deterministic: rank-sort by index
        int v = outb[tid], rank = 0;
#pragma unroll
        for (int j = 0; j < 32; j++) rank += (outb[j] < v);
        g_idx[((b*M_+m) << 5) + rank] = v;
    }
}

// ---------------- GEMM mainloop: pure FFMA2, zero packs ----------------
// acc[pair][out]: pair = 2 consecutive positions packed in f32x2, 4 pairs x 4 outputs.
template<int CIN, int CO, int TP>
__device__ __forceinline__ void mainloop(const float* A, const ull* Wd, ull (&acc)[4][4]) {
    const int OG = CO/4, AS = TP + 4;
    int tid = threadIdx.x;
    int og = tid % OG, pg = tid / OG;
    int o0 = og*4, pp = pg*8;
#pragma unroll
    for (int i = 0; i < 4; i++)
#pragma unroll
        for (int j = 0; j < 4; j++) acc[i][j] = 0ull;
#pragma unroll 4
    for (int c = 0; c < CIN; c++) {
        ulonglong2 a01 = *(const ulonglong2*)&A[c*AS + pp];
        ulonglong2 a23 = *(const ulonglong2*)&A[c*AS + pp + 4];
        ulonglong2 w01 = *(const ulonglong2*)&Wd[c*CO + o0];
        ulonglong2 w23 = *(const ulonglong2*)&Wd[c*CO + o0 + 2];
        fma2(acc[0][0], a01.x, w01.x); fma2(acc[0][1], a01.x, w01.y);
        fma2(acc[0][2], a01.x, w23.x); fma2(acc[0][3], a01.x, w23.y);
        fma2(acc[1][0], a01.y, w01.x); fma2(acc[1][1], a01.y, w01.y);
        fma2(acc[1][2], a01.y, w23.x); fma2(acc[1][3], a01.y, w23.y);
        fma2(acc[2][0], a23.x, w01.x); fma2(acc[2][1], a23.x, w01.y);
        fma2(acc[2][2], a23.x, w23.x); fma2(acc[2][3], a23.x, w23.y);
        fma2(acc[3][0], a23.y, w01.x); fma2(acc[3][1], a23.y, w01.y);
        fma2(acc[3][2], a23.y, w23.x); fma2(acc[3][3], a23.y, w23.y);
    }
}

// ---------------- epilogue: store y + BN partials (transposed layout) ----------------
template<int CO, int TP, int NB>
__device__ __forceinline__ void epi_store_stats(ull (&acc)[4][4], float* A, float* yout,
                                                float* ps, float* pq, int p0) {
    const int OG = CO/4, PG = 256/OG;
    int tid = threadIdx.x;
    int og = tid % OG, pg = tid / OG;
    int o0 = og*4, pp = pg*8;
    float s[4] = {0,0,0,0}, q[4] = {0,0,0,0};
#pragma unroll
    for (int i = 0; i < 4; i++) {
        float2 u[4];
#pragma unroll
        for (int j = 0; j < 4; j++) {
            u[j] = unpk(acc[i][j]);
            s[j] += u[j].x + u[j].y;
            q[j] += u[j].x*u[j].x + u[j].y*u[j].y;
        }
        float4 r0 = make_float4(u[0].x, u[1].x, u[2].x, u[3].x);
        float4 r1 = make_float4(u[0].y, u[1].y, u[2].y, u[3].y);
        *(float4*)&yout[(size_t)(p0 + pp + 2*i  )*CO + o0] = r0;
        *(float4*)&yout[(size_t)(p0 + pp + 2*i+1)*CO + o0] = r1;
    }
    __syncthreads();
    float* rs = A; float* rq = A + PG*CO;
#pragma unroll
    for (int j = 0; j < 4; j++) { rs[pg*CO + o0 + j] = s[j]; rq[pg*CO + o0 + j] = q[j]; }
    __syncthreads();
    if (tid < CO) {
        float S = 0, Q = 0;
#pragma unroll
        for (int g = 0; g < PG; g++) { S += rs[g*CO + tid]; Q += rq[g*CO + tid]; }
        ps[tid*NB + blockIdx.x] = S; pq[tid*NB + blockIdx.x] = Q;
    }
}

// ---------------- stage 1: gather [3 rel-xyz | 64 feat] -> W1 ----------------
__global__ void k_stage1(const float* __restrict__ loc, const float* __restrict__ nl,
                         const float* __restrict__ W1) {
    extern __shared__ float sm[];
    float* A = sm;                         // 67 x 132
    ull*   Wd = (ull*)(sm + 67*132);       // 67 x 64 (duplicated)
    int tid = threadIdx.x;
    for (int i = tid; i < 67*64; i += 256) {
        int c = i >> 6, o = i & 63;
        float w = W1[o*67 + c];
        Wd[i] = pk(w, w);
    }
    int p0 = blockIdx.x * 128;
    int pr = tid >> 1, half = tid & 1;
    int p = p0 + pr;
    int n = g_idx[p];
    int m = (p >> 5) & (M_-1);
    int b = p >> 15;
    if (half == 0) {
#pragma unroll
        for (int d = 0; d < 3; d++)
            A[d*132 + pr] = loc[(b*N_+n)*3 + d] - nl[(b*M_+m)*3 + d];
    }
    const float4* fsrc = (const float4*)(g_featT + ((size_t)(b*N_+n))*64 + half*32);
#pragma unroll
    for (int j = 0; j < 8; j++) {
        float4 v = fsrc[j]; int c = 3 + half*32 + j*4;
        A[(c+0)*132 + pr] = v.x; A[(c+1)*132 + pr] = v.y;
        A[(c+2)*132 + pr] = v.z; A[(c+3)*132 + pr] = v.w;
    }
    __syncthreads();
    ull acc[4][4];
    mainloop<67,64,128>(A, Wd, acc);
    epi_store_stats<64,128,4096>(acc, A, g_y1, g_p1s, g_p1q, p0);
}

// ---------------- stage 2: BN1+ReLU(y1) -> W2 ----------------
__global__ void k_stage2(const float* __restrict__ yin, const float* __restrict__ W2,
                         const float* __restrict__ bn) {
    extern __shared__ float sm[];
    float* A = sm;                         // 64 x 132
    ull*   Wd = (ull*)(sm + 64*132);       // 64 x 64
    __shared__ float sc[64], sb[64];
    int tid = threadIdx.x;
    if (tid < 64) { sc[tid] = bn[tid]; sb[tid] = bn[64 + tid]; }
    for (int i = tid; i < 64*64; i += 256) {
        int c = i >> 6, o = i & 63;
        float w = W2[o*64 + c];
        Wd[i] = pk(w, w);
    }
    __syncthreads();
    int p0 = blockIdx.x * 128;
    int pr = tid >> 1, seg = tid & 1;
    const float4* src = (const float4*)(yin + (size_t)(p0 + pr)*64 + seg*32);
#pragma unroll
    for (int j = 0; j < 8; j++) {
        float4 v = src[j]; int c = seg*32 + j*4;
        A[(c+0)*132 + pr] = fmaxf(fmaf(v.x, sc[c+0], sb[c+0]), 0.f);
        A[(c+1)*132 + pr] = fmaxf(fmaf(v.y, sc[c+1], sb[c+1]), 0.f);
        A[(c+2)*132 + pr] = fmaxf(fmaf(v.z, sc[c+2], sb[c+2]), 0.f);
        A[(c+3)*132 + pr] = fmaxf(fmaf(v.w, sc[c+3], sb[c+3]), 0.f);
    }
    __syncthreads();
    ull acc[4][4];
    mainloop<64,64,128>(A, Wd, acc);
    epi_store_stats<64,128,4096>(acc, A, g_y2, g_p2s, g_p2q, p0);
}

// ---------------- stage 3: BN2+ReLU(y2) -> W3, fused max/min over k ----------------
__global__ void k_stage3(const float* __restrict__ yin, const float* __restrict__ W3,
                         const float* __restrict__ bn) {
    extern __shared__ float sm[];
    float* A = sm;                         // 64 x 68 = 4352 floats
    ull*   Wd = (ull*)(sm + 64*68);        // 64 x 128
    __shared__ float sc[64], sb[64];
    int tid = threadIdx.x;
    if (tid < 64) { sc[tid] = bn[tid]; sb[tid] = bn[64 + tid]; }
    for (int i = tid; i < 64*128; i += 256) {
        int c = i >> 7, o = i & 127;
        float w = W3[o*64 + c];
        Wd[i] = pk(w, w);
    }
    __syncthreads();
    int p0 = blockIdx.x * 64;
    int pr = tid >> 2, seg = tid & 3;
    const float4* src = (const float4*)(yin + (size_t)(p0 + pr)*64 + seg*16);
#pragma unroll
    for (int j = 0; j < 4; j++) {
        float4 v = src[j]; int c = seg*16 + j*4;
        A[(c+0)*68 + pr] = fmaxf(fmaf(v.x, sc[c+0], sb[c+0]), 0.f);
        A[(c+1)*68 + pr] = fmaxf(fmaf(v.y, sc[c+1], sb[c+1]), 0.f);
        A[(c+2)*68 + pr] = fmaxf(fmaf(v.z, sc[c+2], sb[c+2]), 0.f);
        A[(c+3)*68 + pr] = fmaxf(fmaf(v.w, sc[c+3], sb[c+3]), 0.f);
    }
    __syncthreads();
    ull acc[4][4];
    mainloop<64,128,64>(A, Wd, acc);

    // epilogue: stats + per-k-group max/min (no y3 writeback)
    int og = tid & 31, pg = tid >> 5;      // OG=32, PG=8
    int o0 = og*4;
    float s[4] = {0,0,0,0}, q[4] = {0,0,0,0};
    float mx[4], mn[4];
#pragma unroll
    for (int j = 0; j < 4; j++) { mx[j] = -FLT_MAX; mn[j] = FLT_MAX; }
#pragma unroll
    for (int i = 0; i < 4; i++) {
#pragma unroll
        for (int j = 0; j < 4; j++) {
            float2 u = unpk(acc[i][j]);
            s[j] += u.x + u.y;
            q[j] += u.x*u.x + u.y*u.y;
            mx[j] = fmaxf(mx[j], fmaxf(u.x, u.y));
            mn[j] = fminf(mn[j], fminf(u.x, u.y));
        }
    }
    __syncthreads();
    float* rs  = A;          float* rq  = A + 1024;
    float* mxb = A + 2048;   float* mnb = A + 3072;
#pragma unroll
    for (int j = 0; j < 4; j++) {
        rs[pg*128 + o0 + j] = s[j];  rq[pg*128 + o0 + j] = q[j];
        mxb[pg*128 + o0 + j] = mx[j]; mnb[pg*128 + o0 + j] = mn[j];
    }
    __syncthreads();
    if (tid < 128) {
        float S = 0, Q = 0;
#pragma unroll
        for (int g = 0; g < 8; g++) { S += rs[g*128 + tid]; Q += rq[g*128 + tid]; }
        g_p3s[tid*8192 + blockIdx.x] = S; g_p3q[tid*8192 + blockIdx.x] = Q;
    }
    {   // combine max/min: pg 0..3 -> k-group 0, pg 4..7 -> k-group 1
        int grp = tid >> 7, o = tid & 127;
        float Mx = -FLT_MAX, Mn = FLT_MAX;
#pragma unroll
        for (int g = 0; g < 4; g++) {
            Mx = fmaxf(Mx, mxb[(grp*4 + g)*128 + o]);
            Mn = fminf(Mn, mnb[(grp*4 + g)*128 + o]);
        }
        int bm = blockIdx.x*2 + grp;
        g_mx[(size_t)bm*128 + o] = Mx;
        g_mn[(size_t)bm*128 + o] = Mn;
    }
}

// ---------------- BN stats reduce (contiguous reads) ----------------
template<int NB, int CO>
__global__ void k_stats(const float* __restrict__ ps, const float* __restrict__ pq,
                        const float* __restrict__ g, const float* __restrict__ bb,
                        float* bn) {
    __shared__ float ss[256], sq[256];
    int ch = blockIdx.x, tid = threadIdx.x;
    float S = 0, Q = 0;
    for (int i = tid; i < NB; i += 256) { S += ps[ch*NB + i]; Q += pq[ch*NB + i]; }
    ss[tid] = S; sq[tid] = Q; __syncthreads();
    for (int s = 128; s > 0; s >>= 1) {
        if (tid < s) { ss[tid] += ss[tid+s]; sq[tid] += sq[tid+s]; }
        __syncthreads();
    }
    if (tid == 0) {
        float cnt = (float)P_;
        float mu = ss[0]/cnt, var = sq[0]/cnt - mu*mu;
        float scv = g[ch] * rsqrtf(var + 1e-5f);
        bn[ch] = scv; bn[CO + ch] = bb[ch] - mu*scv;
    }
}

// ---------------- final: BN3+ReLU of max/min ----------------
__global__ void k_max(float* __restrict__ out) {
    int m = blockIdx.x, b = blockIdx.y, o = threadIdx.x;
    float scv = g_bn3[o], shv = g_bn3[128 + o];
    size_t bm = (size_t)(b*M_ + m);
    float v = (scv >= 0.f) ? g_mx[bm*128 + o] : g_mn[bm*128 + o];
    out[((size_t)b*128 + o)*M_ + m] = fmaxf(fmaf(v, scv, shv), 0.f);
}

// ---------------- launch ----------------
extern "C" void kernel_launch(void* const* d_in, const int* in_sizes, int n_in,
                              void* d_out, int out_size) {
    const float* loc = (const float*)d_in[0];
    const float* nl  = (const float*)d_in[1];
    const float* ft  = (const float*)d_in[2];
    const float* W1  = (const float*)d_in[3];
    const float* g1  = (const float*)d_in[4];
    const float* b1  = (const float*)d_in[5];
    const float* W2  = (const float*)d_in[6];
    const float* g2  = (const float*)d_in[7];
    const float* b2  = (const float*)d_in[8];
    const float* W3  = (const float*)d_in[9];
    const float* g3  = (const float*)d_in[10];
    const float* b3  = (const float*)d_in[11];
    float* out = (float*)d_out;

    const int S1 = 67*132*4 + 67*64*8;     // 69680
    const int S2 = 64*132*4 + 64*64*8;     // 66560
    const int S3 = 64*68*4  + 64*128*8;    // 82944
    cudaFuncSetAttribute((const void*)k_stage1, cudaFuncAttributeMaxDynamicSharedMemorySize, S1);
    cudaFuncSetAttribute((const void*)k_stage2, cudaFuncAttributeMaxDynamicSharedMemorySize, S2);
    cudaFuncSetAttribute((const void*)k_stage3, cudaFuncAttributeMaxDynamicSharedMemorySize, S3);

    float *y1, *y2, *p1s, *p1q, *p2s, *p2q, *p3s, *p3q, *bn1, *bn2, *bn3;
    cudaGetSymbolAddress((void**)&y1, g_y1);   cudaGetSymbolAddress((void**)&y2, g_y2);
    cudaGetSymbolAddress((void**)&p1s, g_p1s); cudaGetSymbolAddress((void**)&p1q, g_p1q);
    cudaGetSymbolAddress((void**)&p2s, g_p2s); cudaGetSymbolAddress((void**)&p2q, g_p2q);
    cudaGetSymbolAddress((void**)&p3s, g_p3s); cudaGetSymbolAddress((void**)&p3q, g_p3q);
    cudaGetSymbolAddress((void**)&bn1, g_bn1); cudaGetSymbolAddress((void**)&bn2, g_bn2);
    cudaGetSymbolAddress((void**)&bn3, g_bn3);

    k_pre<<<4096 + 16384, 128>>>(ft, loc, nl);                 // idx 0
    k_stage1<<<P_/128, 256, S1>>>(loc, nl, W1);                // idx 1
    k_stats<4096,64><<<64, 256>>>(p1s, p1q, g1, b1, bn1);      // idx 2
    k_stage2<<<P_/128, 256, S2>>>(y1, W2, bn1);                // idx 3
    k_stats<4096,64><<<64, 256>>>(p2s, p2q, g2, b2, bn2);      // idx 4
    k_stage3<<<P_/64, 256, S3>>>(y2, W3, bn2);                 // idx 5  <- profiled next round
    k_stats<8192,128><<<128, 256>>>(p3s, p3q, g3, b3, bn3);    // idx 6
    k_max<<<dim3(M_, B_), 128>>>(out);                         // idx 7
}

// round 12
// speedup vs baseline: 1.5285x; 1.5285x over previous
#include <cuda_runtime.h>
#include <cstdint>
#include <cfloat>

#define B_   16
#define N_   4096
#define M_   1024
#define KNN_ 32
#define P_   (B_*M_*KNN_)   // 524288

typedef unsigned long long ull;

// ---------------- device scratch ----------------
__device__ float g_featT[B_*N_*64];      // [b][n][c]
__device__ int   g_idx[P_];
__device__ float g_y1[P_*64];
__device__ float g_y2[P_*64];
__device__ float g_mx[B_*M_*128];
__device__ float g_mn[B_*M_*128];
__device__ float g_p1s[64*2048], g_p1q[64*2048];    // [ch][blk]
__device__ float g_p2s[64*2048], g_p2q[64*2048];
__device__ float g_p3s[128*4096], g_p3q[128*4096];
__device__ float g_bn1[128];
__device__ float g_bn2[128];
__device__ float g_bn3[256];

// ---------------- f32x2 helpers ----------------
__device__ __forceinline__ ull pk(float a, float b) {
    ull r; asm("mov.b64 %0, {%1, %2};" : "=l"(r) : "f"(a), "f"(b)); return r;
}
__device__ __forceinline__ void fma2(ull& d, ull a, ull b) {
    asm("fma.rn.f32x2 %0, %1, %2, %0;" : "+l"(d) : "l"(a), "l"(b));
}
__device__ __forceinline__ void add2(ull& d, ull a) {
    asm("add.rn.f32x2 %0, %0, %1;" : "+l"(d) : "l"(a));
}
__device__ __forceinline__ float2 unpk(ull v) {
    float2 f; asm("mov.b64 {%0, %1}, %2;" : "=f"(f.x), "=f"(f.y) : "l"(v)); return f;
}

// ---------------- fused pre-pass: transpose + exact KNN ----------------
__device__ __forceinline__ unsigned fkey(float f) {
    unsigned u = __float_as_uint(f);
    return (u & 0x80000000u) ? ~u : (u | 0x80000000u);
}

__global__ void k_pre(const float* __restrict__ f, const float* __restrict__ loc,
                      const float* __restrict__ nl) {
    __shared__ unsigned keys[N_];
    __shared__ unsigned hist[256];
    __shared__ unsigned sh_pfx;
    __shared__ int sh_r, sh_no, sh_ne;
    __shared__ int outb[32];
    __shared__ int eqb[128];
    int bi = blockIdx.x, tid = threadIdx.x;

    if (bi < 4096) {   // transpose [b][c][n] -> [b][n][c]
        float (*tsh)[33] = (float(*)[33])keys;
        int n0 = (bi & 127) * 32, c0 = ((bi >> 7) & 1) * 32, b = bi >> 8;
        int tx = tid & 31, ty = tid >> 5;
#pragma unroll
        for (int i = 0; i < 8; i++)
            tsh[ty + i*4][tx] = f[((size_t)b*64 + c0 + ty + i*4) * N_ + n0 + tx];
        __syncthreads();
#pragma unroll
        for (int i = 0; i < 8; i++)
            g_featT[((size_t)b*N_ + n0 + ty + i*4) * 64 + c0 + tx] = tsh[tx][ty + i*4];
        return;
    }

    int qb = bi - 4096;
    int m = qb & (M_-1), b = qb >> 10;

    float qx = nl[(b*M_+m)*3+0], qy = nl[(b*M_+m)*3+1], qz = nl[(b*M_+m)*3+2];
    float q2 = qx*qx + qy*qy + qz*qz;
    for (int i = tid; i < N_; i += 128) {
        float lx = loc[(b*N_+i)*3+0], ly = loc[(b*N_+i)*3+1], lz = loc[(b*N_+i)*3+2];
        float x2 = lx*lx + ly*ly + lz*lz;
        float dot = qx*lx + qy*ly + qz*lz;
        keys[i] = fkey(q2 + x2 - 2.0f*dot);
    }
    if (tid == 0) { sh_pfx = 0u; sh_r = 31; sh_no = 0; sh_ne = 0; }
    __syncthreads();

    for (int sh = 24; sh >= 0; sh -= 8) {
        for (int i = tid; i < 256; i += 128) hist[i] = 0u;
        __syncthreads();
        unsigned pfx = sh_pfx;
        unsigned hm = (sh == 24) ? 0u : (0xFFFFFFFFu << (sh + 8));
        for (int i = tid; i < N_; i += 128) {
            unsigned k = keys[i];
            if ((k & hm) == pfx) atomicAdd(&hist[(k >> sh) & 255], 1u);
        }
        __syncthreads();
        if (tid == 0) {
            int r = sh_r; unsigned c = 0;
            for (int d = 0; d < 256; d++) {
                unsigned h = hist[d];
                if (c + h > (unsigned)r) { sh_pfx = pfx | ((unsigned)d << sh); sh_r = r - (int)c; break; }
                c += h;
            }
        }
        __syncthreads();
    }
    unsigned T = sh_pfx;
    for (int i = tid; i < N_; i += 128) {
        unsigned k = keys[i];
        if (k < T) { int p = atomicAdd(&sh_no, 1); outb[p] = i; }
        else if (k == T) { int p = atomicAdd(&sh_ne, 1); if (p < 128) eqb[p] = i; }
    }
    __syncthreads();
    if (tid == 0) {
        int need = 32 - sh_no, ne = sh_ne < 128 ? sh_ne : 128;
        for (int t = 0; t < need; t++) {
            int best = 0x7fffffff, bj = 0;
            for (int j = 0; j < ne; j++) if (eqb[j] < best) { best = eqb[j]; bj = j; }
            outb[sh_no + t] = best; eqb[bj] = 0x7fffffff;
        }
    }
    __syncthreads();
    if (tid < 32) {
        int v = outb[tid], rank = 0;
#pragma unroll
        for (int j = 0; j < 32; j++) rank += (outb[j] < v);
        g_idx[((b*M_+m) << 5) + rank] = v;
    }
}

// ---------------- mainloop: 8 pos x 8 out per thread, conflict-free LDS ----------------
// A: [CIN][TP+4] floats (consecutive positions -> f32x2 pairs for free).
// Wsh: [CIN][CO] plain floats (16B/lane contiguous -> conflict-free); pk(w,w) inline.
template<int CIN, int CO, int TP>
__device__ __forceinline__ void mainloop(const float* A, const float* Wsh, ull (&acc)[4][8]) {
    const int OG = CO/8, AS = TP + 4;
    int tid = threadIdx.x;
    int og = tid % OG, pg = tid / OG;
    int o0 = og*4, pp = pg*4;
#pragma unroll
    for (int i = 0; i < 4; i++)
#pragma unroll
        for (int j = 0; j < 8; j++) acc[i][j] = 0ull;
#pragma unroll 2
    for (int c = 0; c < CIN; c++) {
        ulonglong2 aA = *(const ulonglong2*)&A[c*AS + pp];
        ulonglong2 aB = *(const ulonglong2*)&A[c*AS + pp + TP/2];
        float4 w0 = *(const float4*)&Wsh[c*CO + o0];
        float4 w1 = *(const float4*)&Wsh[c*CO + o0 + CO/2];
        ull wd[8];
        wd[0] = pk(w0.x, w0.x); wd[1] = pk(w0.y, w0.y);
        wd[2] = pk(w0.z, w0.z); wd[3] = pk(w0.w, w0.w);
        wd[4] = pk(w1.x, w1.x); wd[5] = pk(w1.y, w1.y);
        wd[6] = pk(w1.z, w1.z); wd[7] = pk(w1.w, w1.w);
        ull pa[4] = {aA.x, aA.y, aB.x, aB.y};
#pragma unroll
        for (int i = 0; i < 4; i++)
#pragma unroll
            for (int j = 0; j < 8; j++) fma2(acc[i][j], pa[i], wd[j]);
    }
}

// ---------------- epilogue for stages 1/2: store y + BN partials ----------------
template<int CO, int TP, int NB>
__device__ __forceinline__ void epi_store_stats(ull (&acc)[4][8], float* A, float* yout,
                                                float* ps, float* pq, int p0) {
    const int OG = CO/8, PG = TP/8;
    int tid = threadIdx.x;
    int og = tid % OG, pg = tid / OG;
    int o0 = og*4, pp = pg*4;
    ull sa[8], sq[8];
#pragma unroll
    for (int j = 0; j < 8; j++) { sa[j] = 0ull; sq[j] = 0ull; }
#pragma unroll
    for (int i = 0; i < 4; i++)
#pragma unroll
        for (int j = 0; j < 8; j++) { add2(sa[j], acc[i][j]); fma2(sq[j], acc[i][j], acc[i][j]); }
#pragma unroll
    for (int i = 0; i < 4; i++) {
        int base = p0 + ((i & 2) ? TP/2 : 0) + pp + (i & 1)*2;
        float2 u[8];
#pragma unroll
        for (int j = 0; j < 8; j++) u[j] = unpk(acc[i][j]);
        *(float4*)&yout[(size_t)base*CO + o0]            = make_float4(u[0].x, u[1].x, u[2].x, u[3].x);
        *(float4*)&yout[(size_t)base*CO + o0 + CO/2]     = make_float4(u[4].x, u[5].x, u[6].x, u[7].x);
        *(float4*)&yout[(size_t)(base+1)*CO + o0]        = make_float4(u[0].y, u[1].y, u[2].y, u[3].y);
        *(float4*)&yout[(size_t)(base+1)*CO + o0 + CO/2] = make_float4(u[4].y, u[5].y, u[6].y, u[7].y);
    }
    __syncthreads();
    float* rs = A; float* rq = A + PG*CO;
#pragma unroll
    for (int j = 0; j < 8; j++) {
        int o = o0 + (j & 3) + (j >= 4 ? CO/2 : 0);
        float2 us = unpk(sa[j]), uq = unpk(sq[j]);
        rs[pg*CO + o] = us.x + us.y;
        rq[pg*CO + o] = uq.x + uq.y;
    }
    __syncthreads();
    if (tid < CO) {
        float S = 0, Q = 0;
#pragma unroll
        for (int g = 0; g < PG; g++) { S += rs[g*CO + tid]; Q += rq[g*CO + tid]; }
        ps[tid*NB + blockIdx.x] = S; pq[tid*NB + blockIdx.x] = Q;
    }
}

// ---------------- stage 1: gather [3 rel-xyz | 64 feat] -> W1 ----------------
__global__ void k_stage1(const float* __restrict__ loc, const float* __restrict__ nl,
                         const float* __restrict__ W1) {
    const int AS = 260;
    extern __shared__ float sm[];
    float* A = sm;                      // 67 x 260
    float* Wsh = sm + 67*AS;            // 67 x 64
    int tid = threadIdx.x;
    for (int i = tid; i < 67*64; i += 256) {
        int c = i >> 6, o = i & 63;
        Wsh[i] = W1[o*67 + c];
    }
    int p0 = blockIdx.x * 256;
    int p = p0 + tid;
    int n = g_idx[p];
    int m = (p >> 5) & (M_-1);
    int b = p >> 15;
#pragma unroll
    for (int d = 0; d < 3; d++)
        A[d*AS + tid] = loc[(b*N_+n)*3 + d] - nl[(b*M_+m)*3 + d];
    const float4* fsrc = (const float4*)(g_featT + ((size_t)(b*N_+n))*64);
#pragma unroll
    for (int j = 0; j < 16; j++) {
        float4 v = fsrc[j]; int c = 3 + j*4;
        A[(c+0)*AS + tid] = v.x; A[(c+1)*AS + tid] = v.y;
        A[(c+2)*AS + tid] = v.z; A[(c+3)*AS + tid] = v.w;
    }
    __syncthreads();
    ull acc[4][8];
    mainloop<67,64,256>(A, Wsh, acc);
    epi_store_stats<64,256,2048>(acc, A, g_y1, g_p1s, g_p1q, p0);
}

// ---------------- stage 2: BN1+ReLU(y1) -> W2 ----------------
__global__ void k_stage2(const float* __restrict__ yin, const float* __restrict__ W2,
                         const float* __restrict__ bn) {
    const int AS = 260;
    extern __shared__ float sm[];
    float* A = sm;                      // 64 x 260
    float* Wsh = sm + 64*AS;            // 64 x 64
    __shared__ float sc[64], sb[64];
    int tid = threadIdx.x;
    if (tid < 64) { sc[tid] = bn[tid]; sb[tid] = bn[64 + tid]; }
    for (int i = tid; i < 64*64; i += 256) {
        int c = i >> 6, o = i & 63;
        Wsh[i] = W2[o*64 + c];
    }
    __syncthreads();
    int p0 = blockIdx.x * 256;
    const float4* src = (const float4*)(yin + (size_t)(p0 + tid)*64);
#pragma unroll
    for (int j = 0; j < 16; j++) {
        float4 v = src[j]; int c = j*4;
        A[(c+0)*AS + tid] = fmaxf(fmaf(v.x, sc[c+0], sb[c+0]), 0.f);
        A[(c+1)*AS + tid] = fmaxf(fmaf(v.y, sc[c+1], sb[c+1]), 0.f);
        A[(c+2)*AS + tid] = fmaxf(fmaf(v.z, sc[c+2], sb[c+2]), 0.f);
        A[(c+3)*AS + tid] = fmaxf(fmaf(v.w, sc[c+3], sb[c+3]), 0.f);
    }
    __syncthreads();
    ull acc[4][8];
    mainloop<64,64,256>(A, Wsh, acc);
    epi_store_stats<64,256,2048>(acc, A, g_y2, g_p2s, g_p2q, p0);
}

// ---------------- stage 3: BN2+ReLU(y2) -> W3, fused stats + max/min over k ----------------
__global__ void k_stage3(const float* __restrict__ yin, const float* __restrict__ W3,
                         const float* __restrict__ bn) {
    const int AS = 132;
    extern __shared__ float sm[];
    float* A = sm;                      // 64 x 132 = 8448 floats
    float* Wsh = sm + 64*AS;            // 64 x 128 = 8192 floats
    __shared__ float sc[64], sb[64];
    int tid = threadIdx.x;
    if (tid < 64) { sc[tid] = bn[tid]; sb[tid] = bn[64 + tid]; }
    for (int i = tid; i < 64*128; i += 256) {
        int c = i >> 7, o = i & 127;
        Wsh[i] = W3[o*64 + c];
    }
    __syncthreads();
    int p0 = blockIdx.x * 128;
    int pr = tid >> 1, seg = tid & 1;
    const float4* src = (const float4*)(yin + (size_t)(p0 + pr)*64 + seg*32);
#pragma unroll
    for (int j = 0; j < 8; j++) {
        float4 v = src[j]; int c = seg*32 + j*4;
        A[(c+0)*AS + pr] = fmaxf(fmaf(v.x, sc[c+0], sb[c+0]), 0.f);
        A[(c+1)*AS + pr] = fmaxf(fmaf(v.y, sc[c+1], sb[c+1]), 0.f);
        A[(c+2)*AS + pr] = fmaxf(fmaf(v.z, sc[c+2], sb[c+2]), 0.f);
        A[(c+3)*AS + pr] = fmaxf(fmaf(v.w, sc[c+3], sb[c+3]), 0.f);
    }
    __syncthreads();
    ull acc[4][8];
    mainloop<64,128,128>(A, Wsh, acc);

    // stats + max/min (no y3 writeback)
    const int OG = 16, PG = 16;
    int og = tid % OG, pg = tid / OG;
    int o0 = og*4;
    ull sa[8], sq[8];
#pragma unroll
    for (int j = 0; j < 8; j++) { sa[j] = 0ull; sq[j] = 0ull; }
    float mx1[8], mn1[8], mx2[8], mn2[8];
#pragma unroll
    for (int j = 0; j < 8; j++) { mx1[j] = mx2[j] = -FLT_MAX; mn1[j] = mn2[j] = FLT_MAX; }
#pragma unroll
    for (int i = 0; i < 4; i++) {
#pragma unroll
        for (int j = 0; j < 8; j++) {
            add2(sa[j], acc[i][j]); fma2(sq[j], acc[i][j], acc[i][j]);
            float2 u = unpk(acc[i][j]);
            float hi = fmaxf(u.x, u.y), lo = fminf(u.x, u.y);
            if (i < 2) { mx1[j] = fmaxf(mx1[j], hi); mn1[j] = fminf(mn1[j], lo); }
            else       { mx2[j] = fmaxf(mx2[j], hi); mn2[j] = fminf(mn2[j], lo); }
        }
    }
    __syncthreads();
    float* rs  = A;            float* rq  = A + 2048;       // 16 x 128 each
    float* mxA = Wsh;          float* mxB = Wsh + 2048;
    float* mnA = Wsh + 4096;   float* mnB = Wsh + 6144;
#pragma unroll
    for (int j = 0; j < 8; j++) {
        int o = o0 + (j & 3) + (j >= 4 ? 64 : 0);
        float2 us = unpk(sa[j]), uq = unpk(sq[j]);
        rs[pg*128 + o] = us.x + us.y;
        rq[pg*128 + o] = uq.x + uq.y;
        mxA[pg*128 + o] = mx1[j]; mnA[pg*128 + o] = mn1[j];
        mxB[pg*128 + o] = mx2[j]; mnB[pg*128 + o] = mn2[j];
    }
    __syncthreads();
    if (tid < 128) {
        float S = 0, Q = 0;
#pragma unroll
        for (int g = 0; g < PG; g++) { S += rs[g*128 + tid]; Q += rq[g*128 + tid]; }
        g_p3s[tid*4096 + blockIdx.x] = S; g_p3q[tid*4096 + blockIdx.x] = Q;
    }
#pragma unroll
    for (int slot = tid; slot < 512; slot += 256) {
        int grp = slot >> 7, o = slot & 127;
        const float* bx = (grp < 2) ? mxA : mxB;
        const float* bn_ = (grp < 2) ? mnA : mnB;
        int pgb = (grp & 1) * 8;
        float Mx = -FLT_MAX, Mn = FLT_MAX;
#pragma unroll
        for (int g = 0; g < 8; g++) {
            Mx = fmaxf(Mx, bx[(pgb + g)*128 + o]);
            Mn = fminf(Mn, bn_[(pgb + g)*128 + o]);
        }
        int bm = blockIdx.x*4 + grp;
        g_mx[(size_t)bm*128 + o] = Mx;
        g_mn[(size_t)bm*128 + o] = Mn;
    }
}

// ---------------- BN stats reduce ----------------
template<int NB, int CO>
__global__ void k_stats(const float* __restrict__ ps, const float* __restrict__ pq,
                        const float* __restrict__ g, const float* __restrict__ bb,
                        float* bn) {
    __shared__ float ss[256], sq[256];
    int ch = blockIdx.x, tid = threadIdx.x;
    float S = 0, Q = 0;
    for (int i = tid; i < NB; i += 256) { S += ps[ch*NB + i]; Q += pq[ch*NB + i]; }
    ss[tid] = S; sq[tid] = Q; __syncthreads();
    for (int s = 128; s > 0; s >>= 1) {
        if (tid < s) { ss[tid] += ss[tid+s]; sq[tid] += sq[tid+s]; }
        __syncthreads();
    }
    if (tid == 0) {
        float cnt = (float)P_;
        float mu = ss[0]/cnt, var = sq[0]/cnt - mu*mu;
        float scv = g[ch] * rsqrtf(var + 1e-5f);
        bn[ch] = scv; bn[CO + ch] = bb[ch] - mu*scv;
    }
}

// ---------------- final: BN3+ReLU of max/min ----------------
__global__ void k_max(float* __restrict__ out) {
    int m = blockIdx.x, b = blockIdx.y, o = threadIdx.x;
    float scv = g_bn3[o], shv = g_bn3[128 + o];
    size_t bm = (size_t)(b*M_ + m);
    float v = (scv >= 0.f) ? g_mx[bm*128 + o] : g_mn[bm*128 + o];
    out[((size_t)b*128 + o)*M_ + m] = fmaxf(fmaf(v, scv, shv), 0.f);
}

// ---------------- launch ----------------
extern "C" void kernel_launch(void* const* d_in, const int* in_sizes, int n_in,
                              void* d_out, int out_size) {
    const float* loc = (const float*)d_in[0];
    const float* nl  = (const float*)d_in[1];
    const float* ft  = (const float*)d_in[2];
    const float* W1  = (const float*)d_in[3];
    const float* g1  = (const float*)d_in[4];
    const float* b1  = (const float*)d_in[5];
    const float* W2  = (const float*)d_in[6];
    const float* g2  = (const float*)d_in[7];
    const float* b2  = (const float*)d_in[8];
    const float* W3  = (const float*)d_in[9];
    const float* g3  = (const float*)d_in[10];
    const float* b3  = (const float*)d_in[11];
    float* out = (float*)d_out;

    const int S1 = (67*260 + 67*64) * 4;   // 86832
    const int S2 = (64*260 + 64*64) * 4;   // 82944
    const int S3 = (64*132 + 64*128) * 4;  // 66560
    cudaFuncSetAttribute((const void*)k_stage1, cudaFuncAttributeMaxDynamicSharedMemorySize, S1);
    cudaFuncSetAttribute((const void*)k_stage2, cudaFuncAttributeMaxDynamicSharedMemorySize, S2);
    cudaFuncSetAttribute((const void*)k_stage3, cudaFuncAttributeMaxDynamicSharedMemorySize, S3);

    float *y1, *y2, *p1s, *p1q, *p2s, *p2q, *p3s, *p3q, *bn1, *bn2, *bn3;
    cudaGetSymbolAddress((void**)&y1, g_y1);   cudaGetSymbolAddress((void**)&y2, g_y2);
    cudaGetSymbolAddress((void**)&p1s, g_p1s); cudaGetSymbolAddress((void**)&p1q, g_p1q);
    cudaGetSymbolAddress((void**)&p2s, g_p2s); cudaGetSymbolAddress((void**)&p2q, g_p2q);
    cudaGetSymbolAddress((void**)&p3s, g_p3s); cudaGetSymbolAddress((void**)&p3q, g_p3q);
    cudaGetSymbolAddress((void**)&bn1, g_bn1); cudaGetSymbolAddress((void**)&bn2, g_bn2);
    cudaGetSymbolAddress((void**)&bn3, g_bn3);

    k_pre<<<4096 + 16384, 128>>>(ft, loc, nl);                 // 0
    k_stage1<<<P_/256, 256, S1>>>(loc, nl, W1);                // 1
    k_stats<2048,64><<<64, 256>>>(p1s, p1q, g1, b1, bn1);      // 2
    k_stage2<<<P_/256, 256, S2>>>(y1, W2, bn1);                // 3
    k_stats<2048,64><<<64, 256>>>(p2s, p2q, g2, b2, bn2);      // 4
    k_stage3<<<P_/128, 256, S3>>>(y2, W3, bn2);                // 5  <- profiled next round
    k_stats<4096,128><<<128, 256>>>(p3s, p3q, g3, b3, bn3);    // 6
    k_max<<<dim3(M_, B_), 128>>>(out);                         // 7
}